// round 5
// baseline (speedup 1.0000x reference)
#include <cuda_runtime.h>
#include <cuda_bf16.h>
#include <cstdint>

#define N_NODE 50000
#define N_EDGE 800000
#define HID 128
#define ZD 128
#define ED 64
#define N_ROWS (N_NODE * 4)

// ---------------- scratch (device globals: no allocation allowed) ----------------
__device__ float g_AB[N_NODE * 256];
__device__ float g_E2[N_ROWS * HID];
__device__ float g_W1T[128 * 256];
__device__ float g_We1T[64 * 128];
__device__ float g_We2T[128 * 128];
__device__ __nv_bfloat16 g_W2hi[128 * 128];   // zW2 [n][k] bf16 hi
__device__ __nv_bfloat16 g_W2lo[128 * 128];   // zW2 [n][k] bf16 lo

__device__ __forceinline__ float silu_f(float x) {
    return x * __fdividef(1.0f, 1.0f + __expf(-x));
}

__device__ __forceinline__ uint32_t smem_u32(const void* p) {
    uint32_t a;
    asm("{ .reg .u64 t; cvta.to.shared.u64 t, %1; cvt.u32.u64 %0, t; }" : "=r"(a) : "l"(p));
    return a;
}

// ldmatrix x4 (four 8x8 b16 tiles), addresses per-lane
__device__ __forceinline__ void ldsm_x4(uint32_t* r, uint32_t addr) {
    asm volatile("ldmatrix.sync.aligned.m8n8.x4.shared.b16 {%0,%1,%2,%3}, [%4];"
        : "=r"(r[0]), "=r"(r[1]), "=r"(r[2]), "=r"(r[3]) : "r"(addr));
}

// D += A*B, m16n8k16 bf16 -> f32
__device__ __forceinline__ void mma_16816(float* d, const uint32_t* a, uint32_t b0, uint32_t b1) {
    asm volatile(
        "mma.sync.aligned.m16n8k16.row.col.f32.bf16.bf16.f32 "
        "{%0,%1,%2,%3}, {%4,%5,%6,%7}, {%8,%9}, {%0,%1,%2,%3};"
        : "+f"(d[0]), "+f"(d[1]), "+f"(d[2]), "+f"(d[3])
        : "r"(a[0]), "r"(a[1]), "r"(a[2]), "r"(a[3]), "r"(b0), "r"(b1));
}

// ---------------- kernel 0: weight transposes + bf16 split ----------------
__global__ void prep_kernel(const float* __restrict__ zW1,
                            const float* __restrict__ zW2,
                            const float* __restrict__ eW1,
                            const float* __restrict__ eW2) {
    int i = blockIdx.x * blockDim.x + threadIdx.x;
    if (i < 32768) {
        int k = i >> 8, c = i & 255;
        g_W1T[i] = (c < 128) ? zW1[c * 256 + k] : zW1[(c - 128) * 256 + 128 + k];
    } else if (i < 40960) {
        int q = i - 32768; int k = q >> 7, n = q & 127;
        g_We1T[q] = eW1[n * 64 + k];
    } else if (i < 57344) {
        int q = i - 40960; int k = q >> 7, n = q & 127;
        g_We2T[q] = eW2[n * 128 + k];
    } else if (i < 73728) {
        int q = i - 57344;
        float v = zW2[q];
        __nv_bfloat16 h = __float2bfloat16(v);
        g_W2hi[q] = h;
        g_W2lo[q] = __float2bfloat16(v - __bfloat162float(h));
    }
}

// ---------------- kernel 1: per-node A|B = silu(z) @ W1eff^T (FFMA) ----------------
__global__ __launch_bounds__(256, 2)
void nodeAB_kernel(const float* __restrict__ z_embed) {
    extern __shared__ float sm[];
    float* sP = sm;
    float* sW = sm + 16384;
    const int tid = threadIdx.x;
    const int m0 = blockIdx.x * 128;
    const int half = blockIdx.y;

    #pragma unroll
    for (int it = 0; it < 16; ++it) {
        int m = it * 8 + (tid >> 5);
        int k4 = (tid & 31) * 4;
        int node = m0 + m;
        float4 v = make_float4(0.f, 0.f, 0.f, 0.f);
        if (node < N_NODE) v = *reinterpret_cast<const float4*>(&z_embed[node * ZD + k4]);
        v.x = silu_f(v.x); v.y = silu_f(v.y); v.z = silu_f(v.z); v.w = silu_f(v.w);
        *reinterpret_cast<float4*>(&sP[m * 128 + k4]) = v;
    }

    const int ty = tid >> 4, tx = tid & 15;
    const int mB = ty * 8, nB = tx * 8;
    float acc[8][8];
    #pragma unroll
    for (int r = 0; r < 8; ++r)
        #pragma unroll
        for (int c = 0; c < 8; ++c) acc[r][c] = 0.f;

    for (int c64 = 0; c64 < 2; ++c64) {
        if (c64) __syncthreads();
        #pragma unroll
        for (int it = 0; it < 8; ++it) {
            int kr = it * 8 + (tid >> 5);
            int n4 = (tid & 31) * 4;
            float4 w = *reinterpret_cast<const float4*>(
                &g_W1T[(c64 * 64 + kr) * 256 + half * 128 + n4]);
            *reinterpret_cast<float4*>(&sW[kr * 132 + n4]) = w;
        }
        __syncthreads();
        #pragma unroll 4
        for (int k = 0; k < 64; ++k) {
            float a[8], b[8];
            #pragma unroll
            for (int r = 0; r < 8; ++r) a[r] = sP[(mB + r) * 128 + c64 * 64 + k];
            float4 b0 = *reinterpret_cast<const float4*>(&sW[k * 132 + nB]);
            float4 b1 = *reinterpret_cast<const float4*>(&sW[k * 132 + nB + 4]);
            b[0]=b0.x; b[1]=b0.y; b[2]=b0.z; b[3]=b0.w;
            b[4]=b1.x; b[5]=b1.y; b[6]=b1.z; b[7]=b1.w;
            #pragma unroll
            for (int r = 0; r < 8; ++r)
                #pragma unroll
                for (int c = 0; c < 8; ++c) acc[r][c] = fmaf(a[r], b[c], acc[r][c]);
        }
    }

    #pragma unroll
    for (int r = 0; r < 8; ++r) {
        int node = m0 + mB + r;
        if (node < N_NODE) {
            #pragma unroll
            for (int c = 0; c < 8; c += 4) {
                float4 o = make_float4(acc[r][c], acc[r][c+1], acc[r][c+2], acc[r][c+3]);
                *reinterpret_cast<float4*>(&g_AB[node * 256 + half * 128 + nB + c]) = o;
            }
        }
    }
}

// ---------------- kernel 2: per-(node,orb) e-branch (FFMA) ----------------
__global__ __launch_bounds__(256, 1)
void nodeE_kernel(const float* __restrict__ e_embed) {
    extern __shared__ float sm[];
    float* sX  = sm;
    float* sW1 = sm + 8192;
    float* sH  = sm + 16640;
    float* sW2 = sm + 33024;
    const int tid = threadIdx.x;
    const int r0 = blockIdx.x * 128;

    #pragma unroll
    for (int it = 0; it < 8; ++it) {
        int m = it * 16 + (tid >> 4);
        int k4 = (tid & 15) * 4;
        int row = r0 + m;
        float4 v = make_float4(0.f, 0.f, 0.f, 0.f);
        if (row < N_ROWS) v = *reinterpret_cast<const float4*>(&e_embed[row * ED + k4]);
        v.x = silu_f(v.x); v.y = silu_f(v.y); v.z = silu_f(v.z); v.w = silu_f(v.w);
        *reinterpret_cast<float4*>(&sX[m * 64 + k4]) = v;
    }
    #pragma unroll
    for (int it = 0; it < 8; ++it) {
        int kr = it * 8 + (tid >> 5);
        int n4 = (tid & 31) * 4;
        float4 w = *reinterpret_cast<const float4*>(&g_We1T[kr * 128 + n4]);
        *reinterpret_cast<float4*>(&sW1[kr * 132 + n4]) = w;
    }
    #pragma unroll
    for (int it = 0; it < 16; ++it) {
        int kr = it * 8 + (tid >> 5);
        int n4 = (tid & 31) * 4;
        float4 w = *reinterpret_cast<const float4*>(&g_We2T[kr * 128 + n4]);
        *reinterpret_cast<float4*>(&sW2[kr * 132 + n4]) = w;
    }
    __syncthreads();

    const int ty = tid >> 4, tx = tid & 15;
    const int mB = ty * 8, nB = tx * 8;
    float acc[8][8];
    #pragma unroll
    for (int r = 0; r < 8; ++r)
        #pragma unroll
        for (int c = 0; c < 8; ++c) acc[r][c] = 0.f;

    #pragma unroll 4
    for (int k = 0; k < 64; ++k) {
        float a[8], b[8];
        #pragma unroll
        for (int r = 0; r < 8; ++r) a[r] = sX[(mB + r) * 64 + k];
        float4 b0 = *reinterpret_cast<const float4*>(&sW1[k * 132 + nB]);
        float4 b1 = *reinterpret_cast<const float4*>(&sW1[k * 132 + nB + 4]);
        b[0]=b0.x; b[1]=b0.y; b[2]=b0.z; b[3]=b0.w;
        b[4]=b1.x; b[5]=b1.y; b[6]=b1.z; b[7]=b1.w;
        #pragma unroll
        for (int r = 0; r < 8; ++r)
            #pragma unroll
            for (int c = 0; c < 8; ++c) acc[r][c] = fmaf(a[r], b[c], acc[r][c]);
    }

    #pragma unroll
    for (int r = 0; r < 8; ++r) {
        #pragma unroll
        for (int c = 0; c < 8; c += 4) {
            float4 h;
            h.x = silu_f(acc[r][c]);   h.y = silu_f(acc[r][c+1]);
            h.z = silu_f(acc[r][c+2]); h.w = silu_f(acc[r][c+3]);
            *reinterpret_cast<float4*>(&sH[(mB + r) * 128 + nB + c]) = h;
        }
    }
    __syncthreads();

    float acc2[8][8];
    #pragma unroll
    for (int r = 0; r < 8; ++r)
        #pragma unroll
        for (int c = 0; c < 8; ++c) acc2[r][c] = 0.f;

    #pragma unroll 4
    for (int k = 0; k < 128; ++k) {
        float a[8], b[8];
        #pragma unroll
        for (int r = 0; r < 8; ++r) a[r] = sH[(mB + r) * 128 + k];
        float4 b0 = *reinterpret_cast<const float4*>(&sW2[k * 132 + nB]);
        float4 b1 = *reinterpret_cast<const float4*>(&sW2[k * 132 + nB + 4]);
        b[0]=b0.x; b[1]=b0.y; b[2]=b0.z; b[3]=b0.w;
        b[4]=b1.x; b[5]=b1.y; b[6]=b1.z; b[7]=b1.w;
        #pragma unroll
        for (int r = 0; r < 8; ++r)
            #pragma unroll
            for (int c = 0; c < 8; ++c) acc2[r][c] = fmaf(a[r], b[c], acc2[r][c]);
    }

    #pragma unroll
    for (int r = 0; r < 8; ++r) {
        int row = r0 + mB + r;
        if (row < N_ROWS) {
            #pragma unroll
            for (int c = 0; c < 8; c += 4) {
                float4 o = make_float4(acc2[r][c], acc2[r][c+1], acc2[r][c+2], acc2[r][c+3]);
                *reinterpret_cast<float4*>(&g_E2[row * 128 + nB + c]) = o;
            }
        }
    }
}

// ---------------- kernel 3: per-edge second layer via mma.sync bf16 3-pass ----------------
// tile: 64 edges x 128 hid, K=128. 256 threads, 2 CTAs/SM.
// smem tiles are [rows][128 bf16] with 256B row stride; 16B chunks XOR-swizzled:
//   addr(row, chunk) = row*256 + ((chunk ^ (row & 7)) << 4)
#define OFF_AHI  0         // 64x128 bf16 hi   (16384)
#define OFF_ALO  16384     // 64x128 bf16 lo   (16384)
#define OFF_WHI  32768     // 128x128 bf16 hi  (32768)
#define OFF_WLO  65536     // 128x128 bf16 lo  (32768)
#define OFF_SG   0         // 64x132 f32 g tile (33792, reuses A + head of Whi)
#define OFF_B2   98304     // 512
#define OFF_J    98816     // 256
#define SMEM_EDGE 99072

__global__ __launch_bounds__(256, 2)
void edge_mma_kernel(const int* __restrict__ idx_i, const int* __restrict__ idx_j,
                     const float* __restrict__ zb1, const float* __restrict__ zb2,
                     float* __restrict__ out) {
    extern __shared__ char smc[];
    const uint32_t sb = smem_u32(smc);
    float* sG  = reinterpret_cast<float*>(smc + OFF_SG);
    float* sB2 = reinterpret_cast<float*>(smc + OFF_B2);
    int*   sJ  = reinterpret_cast<int*>(smc + OFF_J);
    const int tid = threadIdx.x;
    const int lane = tid & 31;
    const int wid = tid >> 5;
    const int e0 = blockIdx.x * 64;

    if (tid < 128) sB2[tid] = zb2[tid];
    if (tid < 64)  sJ[tid] = idx_j[e0 + tid];

    // W tiles: g_W2hi/lo [n][k] -> swizzled smem (16B chunks)
    #pragma unroll
    for (int it = 0; it < 8; ++it) {
        int idx = it * 256 + tid;            // 0..2047
        int n = idx >> 4, c = idx & 15;
        uint32_t d = (uint32_t)(n * 256 + ((c ^ (n & 7)) << 4));
        *reinterpret_cast<uint4*>(smc + OFF_WHI + d) = reinterpret_cast<const uint4*>(g_W2hi)[idx];
        *reinterpret_cast<uint4*>(smc + OFF_WLO + d) = reinterpret_cast<const uint4*>(g_W2lo)[idx];
    }

    // A tiles: s = silu(A[i]+B[j]+zb1), bf16 hi/lo split, swizzled
    #pragma unroll
    for (int it = 0; it < 8; ++it) {
        int m = it * 8 + wid;
        int k4 = lane * 4;
        int e = e0 + m;
        int i = __ldg(&idx_i[e]);
        int j = __ldg(&idx_j[e]);
        float4 a = *reinterpret_cast<const float4*>(&g_AB[i * 256 + k4]);
        float4 b = *reinterpret_cast<const float4*>(&g_AB[j * 256 + 128 + k4]);
        float4 bias = __ldg(reinterpret_cast<const float4*>(&zb1[k4]));
        float s0 = silu_f(a.x + b.x + bias.x);
        float s1 = silu_f(a.y + b.y + bias.y);
        float s2 = silu_f(a.z + b.z + bias.z);
        float s3 = silu_f(a.w + b.w + bias.w);
        __nv_bfloat16 h0 = __float2bfloat16(s0), h1 = __float2bfloat16(s1);
        __nv_bfloat16 h2 = __float2bfloat16(s2), h3 = __float2bfloat16(s3);
        __nv_bfloat16 l0 = __float2bfloat16(s0 - __bfloat162float(h0));
        __nv_bfloat16 l1 = __float2bfloat16(s1 - __bfloat162float(h1));
        __nv_bfloat16 l2 = __float2bfloat16(s2 - __bfloat162float(h2));
        __nv_bfloat16 l3 = __float2bfloat16(s3 - __bfloat162float(h3));
        uint2 hp, lp;
        hp.x = (uint32_t)__bfloat16_as_ushort(h0) | ((uint32_t)__bfloat16_as_ushort(h1) << 16);
        hp.y = (uint32_t)__bfloat16_as_ushort(h2) | ((uint32_t)__bfloat16_as_ushort(h3) << 16);
        lp.x = (uint32_t)__bfloat16_as_ushort(l0) | ((uint32_t)__bfloat16_as_ushort(l1) << 16);
        lp.y = (uint32_t)__bfloat16_as_ushort(l2) | ((uint32_t)__bfloat16_as_ushort(l3) << 16);
        int chunk = lane >> 1;
        uint32_t d = (uint32_t)(m * 256 + ((chunk ^ (m & 7)) << 4) + (lane & 1) * 8);
        *reinterpret_cast<uint2*>(smc + OFF_AHI + d) = hp;
        *reinterpret_cast<uint2*>(smc + OFF_ALO + d) = lp;
    }
    __syncthreads();

    // --- MMA: warp grid 2(m) x 4(n); warp tile 32x32; 3 passes over K=128 ---
    const int warpM = wid & 1;          // 0..1
    const int warpN = wid >> 1;         // 0..3
    float acc[2][4][4];
    #pragma unroll
    for (int mi = 0; mi < 2; ++mi)
        #pragma unroll
        for (int ni = 0; ni < 4; ++ni)
            #pragma unroll
            for (int q = 0; q < 4; ++q) acc[mi][ni][q] = 0.f;

    // per-lane ldmatrix row indices
    const int aRow0 = warpM * 32 + (lane & 15);           // + mi*16
    const int aSel  = lane >> 4;                           // chunk +0/+1
    const int bRow0 = warpN * 32 + (lane & 7) + ((lane >> 4) << 3);  // + g*16
    const int bSel  = (lane >> 3) & 1;

    #pragma unroll
    for (int p = 0; p < 3; ++p) {
        const uint32_t aB = sb + ((p == 2) ? OFF_ALO : OFF_AHI);
        const uint32_t bB = sb + ((p == 1) ? OFF_WLO : OFF_WHI);
        #pragma unroll
        for (int kk = 0; kk < 8; ++kk) {
            const int c0 = kk * 2;
            uint32_t af[2][4], bf[2][4];
            #pragma unroll
            for (int mi = 0; mi < 2; ++mi) {
                int row = aRow0 + mi * 16;
                ldsm_x4(af[mi], aB + row * 256 + (((c0 + aSel) ^ (row & 7)) << 4));
            }
            #pragma unroll
            for (int g = 0; g < 2; ++g) {
                int row = bRow0 + g * 16;
                ldsm_x4(bf[g], bB + row * 256 + (((c0 + bSel) ^ (row & 7)) << 4));
            }
            #pragma unroll
            for (int mi = 0; mi < 2; ++mi)
                #pragma unroll
                for (int ni = 0; ni < 4; ++ni)
                    mma_16816(acc[mi][ni], af[mi], bf[ni >> 1][(ni & 1) * 2], bf[ni >> 1][(ni & 1) * 2 + 1]);
        }
    }
    __syncthreads();   // all smem tile reads done; safe to overwrite with sG

    // g = 1 + z2 + zb2 -> sG [64][132]
    {
        const int gr = warpM * 32 + (lane >> 2);
        const int gc = warpN * 32 + 2 * (lane & 3);
        #pragma unroll
        for (int mi = 0; mi < 2; ++mi) {
            #pragma unroll
            for (int ni = 0; ni < 4; ++ni) {
                int col = gc + ni * 8;
                float2 v0, v1;
                v0.x = 1.f + acc[mi][ni][0] + sB2[col];
                v0.y = 1.f + acc[mi][ni][1] + sB2[col + 1];
                v1.x = 1.f + acc[mi][ni][2] + sB2[col];
                v1.y = 1.f + acc[mi][ni][3] + sB2[col + 1];
                int r0 = gr + mi * 16;
                *reinterpret_cast<float2*>(&sG[r0 * 132 + col]) = v0;
                *reinterpret_cast<float2*>(&sG[(r0 + 8) * 132 + col]) = v1;
            }
        }
    }
    __syncthreads();

    // epilogue: out[e, orb, h] = E2[j, orb, h] * g[e, h]
    const int h = lane * 4;
    const int orb = wid & 3;
    const int msel = wid >> 2;   // 0/1
    #pragma unroll 4
    for (int it = 0; it < 32; ++it) {
        int m = it * 2 + msel;
        int j = sJ[m];
        float4 ev = *reinterpret_cast<const float4*>(&g_E2[(j * 4 + orb) * 128 + h]);
        float4 g  = *reinterpret_cast<const float4*>(&sG[m * 132 + h]);
        float4 o;
        o.x = ev.x * g.x; o.y = ev.y * g.y; o.z = ev.z * g.z; o.w = ev.w * g.w;
        size_t off = ((size_t)(e0 + m) * 4 + orb) * 128 + h;
        __stcs(reinterpret_cast<float4*>(&out[off]), o);
    }
}

// ---------------- launch ----------------
extern "C" void kernel_launch(void* const* d_in, const int* in_sizes, int n_in,
                              void* d_out, int out_size) {
    const float* z_embed = (const float*)d_in[0];
    const float* e_embed = (const float*)d_in[1];
    const int*   idx_i   = (const int*)d_in[2];
    const int*   idx_j   = (const int*)d_in[3];
    const float* zW1     = (const float*)d_in[4];
    const float* zb1     = (const float*)d_in[5];
    const float* zW2     = (const float*)d_in[6];
    const float* zb2     = (const float*)d_in[7];
    const float* eW1     = (const float*)d_in[8];
    const float* eW2     = (const float*)d_in[9];
    float* out = (float*)d_out;

    const int SMEM1 = (16384 + 64 * 132) * 4;
    const int SMEM2 = (8192 + 64 * 132 + 16384 + 128 * 132) * 4;
    cudaFuncSetAttribute(nodeAB_kernel, cudaFuncAttributeMaxDynamicSharedMemorySize, SMEM1);
    cudaFuncSetAttribute(nodeE_kernel,  cudaFuncAttributeMaxDynamicSharedMemorySize, SMEM2);
    cudaFuncSetAttribute(edge_mma_kernel, cudaFuncAttributeMaxDynamicSharedMemorySize, SMEM_EDGE);

    prep_kernel<<<288, 256>>>(zW1, zW2, eW1, eW2);
    nodeAB_kernel<<<dim3(391, 2), 256, SMEM1>>>(z_embed);
    nodeE_kernel<<<1563, 256, SMEM2>>>(e_embed);
    edge_mma_kernel<<<12500, 256, SMEM_EDGE>>>(idx_i, idx_j, zb1, zb2, out);
}